// round 3
// baseline (speedup 1.0000x reference)
#include <cuda_runtime.h>
#include <math.h>

// Problem constants (fixed by the reference setup_inputs)
#define M     16384
#define DIMS  64
#define NBIN  32
#define HID   100
#define CDIM  64

// Scratch (no cudaMalloc allowed): hidden activations transposed [300][M], and
// per-dim log-derivs for a deterministic reduction.
__device__ float g_H [3 * HID * M];
__device__ float g_ld[DIMS * M];

// ---------------------------------------------------------------------------
// Kernel 1: H_T[j][r] = silu(cond[r,:] @ W1[:,j] + b1[j]) for the 3 MLPs
// (j in [0,100) -> w, [100,200) -> h, [200,300) -> s). Block = 128 rows.
// cond tile staged in smem transposed; W1 columns read as uniform LDG (L1/L2
// resident, same address for whole warp); H stored as float4 (coalesced).
// ---------------------------------------------------------------------------
__global__ __launch_bounds__(256) void k1_hidden(
    const float* __restrict__ cond,
    const float* __restrict__ wW1, const float* __restrict__ wb1,
    const float* __restrict__ hW1, const float* __restrict__ hb1,
    const float* __restrict__ sW1, const float* __restrict__ sb1)
{
    __shared__ __align__(16) float condT[CDIM * 132];  // [i][r], stride 132 (16B-aligned rows)
    const int tid     = threadIdx.x;
    const int rowBase = blockIdx.x * 128;

    for (int idx = tid; idx < 128 * CDIM; idx += 256) {
        int i  = idx & 63;
        int rl = idx >> 6;
        condT[i * 132 + rl] = cond[(rowBase + rl) * CDIM + i];
    }
    __syncthreads();

    const int warp = tid >> 5;
    const int lane = tid & 31;

    for (int j = warp; j < 3 * HID; j += 8) {
        const float* W1; const float* b1; int jj;
        if (j < HID)          { W1 = wW1; b1 = wb1; jj = j; }
        else if (j < 2 * HID) { W1 = hW1; b1 = hb1; jj = j - HID; }
        else                  { W1 = sW1; b1 = sb1; jj = j - 2 * HID; }

        float bv = __ldg(&b1[jj]);
        float a0 = bv, a1 = bv, a2 = bv, a3 = bv;
        #pragma unroll 8
        for (int i = 0; i < CDIM; i++) {
            float  wv = __ldg(&W1[i * HID + jj]);                       // uniform across warp
            float4 c4 = *reinterpret_cast<const float4*>(&condT[i * 132 + lane * 4]);
            a0 = fmaf(c4.x, wv, a0);
            a1 = fmaf(c4.y, wv, a1);
            a2 = fmaf(c4.z, wv, a2);
            a3 = fmaf(c4.w, wv, a3);
        }
        // silu
        a0 = a0 / (1.0f + expf(-a0));
        a1 = a1 / (1.0f + expf(-a1));
        a2 = a2 / (1.0f + expf(-a2));
        a3 = a3 / (1.0f + expf(-a3));
        *reinterpret_cast<float4*>(&g_H[j * M + rowBase + lane * 4]) =
            make_float4(a0, a1, a2, a3);
    }
}

// ---------------------------------------------------------------------------
// Kernel 2: fused GEMM2 + rational-quadratic spline.
// Grid: (M/256 row tiles, 64 dims). One thread = one (row, dim).
// W2 slices for this dim cached in smem and read via broadcast LDS.128.
// The s-network only evaluates the 2 needed columns (idx, idx+1 / wrap).
// ---------------------------------------------------------------------------
__global__ __launch_bounds__(256) void k2_spline(
    const float* __restrict__ x,
    const int*   __restrict__ pmask,
    const float* __restrict__ wW2, const float* __restrict__ wb2,
    const float* __restrict__ hW2, const float* __restrict__ hb2,
    const float* __restrict__ sW2, const float* __restrict__ sb2,
    float* __restrict__ out)
{
    __shared__ __align__(16) float sWw[HID][32];
    __shared__ __align__(16) float sWh[HID][32];
    __shared__ float sWs[HID][33];
    __shared__ float sbw[32], sbh[32], sbs[33];

    const int tid = threadIdx.x;
    const int d   = blockIdx.y;

    for (int idx = tid; idx < HID * 32; idx += 256) {
        int k = idx >> 5, j = idx & 31;
        sWw[k][j] = wW2[k * (DIMS * NBIN) + d * 32 + j];
        sWh[k][j] = hW2[k * (DIMS * NBIN) + d * 32 + j];
    }
    for (int idx = tid; idx < HID * 33; idx += 256) {
        int k = idx / 33, j = idx - k * 33;
        sWs[k][j] = sW2[k * (DIMS * (NBIN + 1)) + d * 33 + j];
    }
    if (tid < 32) { sbw[tid] = wb2[d * 32 + tid]; sbh[tid] = hb2[d * 32 + tid]; }
    if (tid < 33) { sbs[tid] = sb2[d * 33 + tid]; }
    __syncthreads();

    const int   r  = blockIdx.x * 256 + tid;
    const float xv = __ldg(&x[r * DIMS + d]);

    float acc[32];

    // ---------------- pass 1: width logits -> softmax -> bin search ----------
    #pragma unroll
    for (int j = 0; j < 32; j++) acc[j] = sbw[j];
    #pragma unroll 2
    for (int k = 0; k < HID; k++) {
        float hv = __ldg(&g_H[k * M + r]);
        const float4* row = reinterpret_cast<const float4*>(sWw[k]);
        #pragma unroll
        for (int q = 0; q < 8; q++) {
            float4 v = row[q];
            acc[4*q+0] = fmaf(hv, v.x, acc[4*q+0]);
            acc[4*q+1] = fmaf(hv, v.y, acc[4*q+1]);
            acc[4*q+2] = fmaf(hv, v.z, acc[4*q+2]);
            acc[4*q+3] = fmaf(hv, v.w, acc[4*q+3]);
        }
    }
    float mx = acc[0];
    #pragma unroll
    for (int j = 1; j < 32; j++) mx = fmaxf(mx, acc[j]);
    float S = 0.0f;
    #pragma unroll
    for (int j = 0; j < 32; j++) { acc[j] = expf(acc[j] - mx); S += acc[j]; }
    float invS = 0.68f / S;  // (1 - EPS_BIN*NB) / S

    int   idx = 0;
    float cwk = -1.0f, cwn = 1.0f, cum = 0.0f;
    bool  found = false;
    #pragma unroll
    for (int j = 0; j < 32; j++) {
        float wj   = fmaf(acc[j], invS, 0.01f);
        cum += wj;
        float knot = (j == 31) ? 1.0f : fmaf(2.0f, cum, -1.0f);
        bool  ge   = (j < 31) && (xv >= knot);
        if (ge)             { idx = j + 1; cwk = knot; }
        if (!found && !ge)  { cwn = knot; found = true; }  // first knot > x == cw[idx+1]
    }
    float wk = cwn - cwk;

    // ---------------- pass 2: height logits -> softmax -> gather at idx ------
    #pragma unroll
    for (int j = 0; j < 32; j++) acc[j] = sbh[j];
    #pragma unroll 2
    for (int k = 0; k < HID; k++) {
        float hv = __ldg(&g_H[(HID + k) * M + r]);
        const float4* row = reinterpret_cast<const float4*>(sWh[k]);
        #pragma unroll
        for (int q = 0; q < 8; q++) {
            float4 v = row[q];
            acc[4*q+0] = fmaf(hv, v.x, acc[4*q+0]);
            acc[4*q+1] = fmaf(hv, v.y, acc[4*q+1]);
            acc[4*q+2] = fmaf(hv, v.z, acc[4*q+2]);
            acc[4*q+3] = fmaf(hv, v.w, acc[4*q+3]);
        }
    }
    float mx2 = acc[0];
    #pragma unroll
    for (int j = 1; j < 32; j++) mx2 = fmaxf(mx2, acc[j]);
    float S2 = 0.0f;
    #pragma unroll
    for (int j = 0; j < 32; j++) { acc[j] = expf(acc[j] - mx2); S2 += acc[j]; }
    float invS2 = 0.68f / S2;

    float chk = -1.0f, chn = 1.0f;
    cum = 0.0f;
    #pragma unroll
    for (int j = 0; j < 32; j++) {
        float hj   = fmaf(acc[j], invS2, 0.01f);
        cum += hj;
        float knot = (j == 31) ? 1.0f : fmaf(2.0f, cum, -1.0f);
        if (j + 1 == idx) chk = knot;
        if (j     == idx) chn = knot;   // j==31 forced to 1.0 handles idx==31
    }
    float hk = chn - chk;

    // ---------------- pass 3: only the two needed derivative columns ---------
    int  pmd = __ldg(&pmask[d]);
    int  c1  = (pmd != 0 && idx == NBIN - 1) ? 0 : (idx + 1);
    float a0 = sbs[idx], a1 = sbs[c1];
    #pragma unroll 4
    for (int k = 0; k < HID; k++) {
        float hv = __ldg(&g_H[(2 * HID + k) * M + r]);
        float w0 = sWs[k][idx];
        float w1 = sWs[k][c1];
        a0 = fmaf(hv, w0, a0);
        a1 = fmaf(hv, w1, a1);
    }
    // softplus(v) = max(v,0) + log1p(exp(-|v|))  (accurate, overflow-safe)
    float dk  = 0.01f + fmaxf(a0, 0.0f) + log1pf(expf(-fabsf(a0)));
    float dk1 = 0.01f + fmaxf(a1, 0.0f) + log1pf(expf(-fabsf(a1)));

    // ---------------- rational-quadratic evaluation --------------------------
    float delta = hk / wk;
    float theta = (xv - cwk) / wk;
    float omt   = 1.0f - theta;
    float t1m   = theta * omt;
    float denom = delta + (dk1 + dk - 2.0f * delta) * t1m;
    float th2   = theta * theta;
    float yv    = chk + hk * (delta * th2 + dk * t1m) / denom;
    float dnum  = dk1 * th2 + 2.0f * delta * t1m + dk * omt * omt;
    float deriv = (delta * delta) * dnum / (denom * denom);

    out[r * DIMS + d] = yv;
    g_ld[d * M + r]   = logf(deriv);
}

// ---------------------------------------------------------------------------
// Kernel 3: deterministic ladJ reduction (sum of log-derivs over dims).
// ---------------------------------------------------------------------------
__global__ __launch_bounds__(256) void k3_ladj(float* __restrict__ out)
{
    int r = blockIdx.x * 256 + threadIdx.x;
    float s = 0.0f;
    #pragma unroll
    for (int d = 0; d < DIMS; d++) s += g_ld[d * M + r];
    out[M * DIMS + r] = s;
}

// ---------------------------------------------------------------------------
extern "C" void kernel_launch(void* const* d_in, const int* in_sizes, int n_in,
                              void* d_out, int out_size)
{
    const float* x    = (const float*)d_in[0];
    const float* cond = (const float*)d_in[1];
    const int*   pm   = (const int*)  d_in[2];
    const float* wW1  = (const float*)d_in[3];
    const float* wb1  = (const float*)d_in[4];
    const float* wW2  = (const float*)d_in[5];
    const float* wb2  = (const float*)d_in[6];
    const float* hW1  = (const float*)d_in[7];
    const float* hb1  = (const float*)d_in[8];
    const float* hW2  = (const float*)d_in[9];
    const float* hb2  = (const float*)d_in[10];
    const float* sW1  = (const float*)d_in[11];
    const float* sb1  = (const float*)d_in[12];
    const float* sW2  = (const float*)d_in[13];
    const float* sb2  = (const float*)d_in[14];
    float* out = (float*)d_out;

    k1_hidden<<<M / 128, 256>>>(cond, wW1, wb1, hW1, hb1, sW1, sb1);
    k2_spline<<<dim3(M / 256, DIMS), 256>>>(x, pm, wW2, wb2, hW2, hb2, sW2, sb2, out);
    k3_ladj<<<M / 256, 256>>>(out);
}

// round 4
// speedup vs baseline: 1.1191x; 1.1191x over previous
#include <cuda_runtime.h>
#include <math.h>

// Problem constants (fixed by the reference setup_inputs)
#define M     16384
#define DIMS  64
#define NBIN  32
#define HID   100
#define CDIM  64

// Scratch (no cudaMalloc allowed): hidden activations transposed [300][M], and
// per-dim log-derivs for a deterministic reduction.
__device__ float g_H [3 * HID * M];
__device__ float g_ld[DIMS * M];

// ---------------------------------------------------------------------------
// Kernel 1: H_T[j][r] = silu(cond[r,:] @ W1[:,j] + b1[j]) for the 3 MLPs.
// Grid: (M/64 row tiles, 3 MLPs) = 768 CTAs (full chip, ~5 CTAs/SM).
// W1 transposed in smem ([j][i], pad 68 -> odd float4 stride, conflict-free),
// cond tile in smem. Each thread: 25 j-columns, inner loop 4:1 FMA:LDS.
// ---------------------------------------------------------------------------
__global__ __launch_bounds__(256) void k1_hidden(
    const float* __restrict__ cond,
    const float* __restrict__ wW1, const float* __restrict__ wb1,
    const float* __restrict__ hW1, const float* __restrict__ hb1,
    const float* __restrict__ sW1, const float* __restrict__ sb1)
{
    __shared__ __align__(16) float W1T [HID][68];   // [j][i]
    __shared__ __align__(16) float condS[64][68];   // [row][i]
    __shared__ float biasS[HID];

    const int tid     = threadIdx.x;
    const int mlp     = blockIdx.y;
    const int rowBase = blockIdx.x * 64;

    const float* W1 = (mlp == 0) ? wW1 : (mlp == 1) ? hW1 : sW1;
    const float* b1 = (mlp == 0) ? wb1 : (mlp == 1) ? hb1 : sb1;

    for (int idx = tid; idx < CDIM * HID; idx += 256) {
        int i = idx / HID, j = idx - i * HID;     // global read coalesced
        W1T[j][i] = W1[idx];
    }
    for (int idx = tid; idx < 64 * CDIM; idx += 256) {
        int rl = idx >> 6, i = idx & 63;
        condS[rl][i] = cond[(rowBase + rl) * CDIM + i];
    }
    if (tid < HID) biasS[tid] = b1[tid];
    __syncthreads();

    const int row = tid & 63;
    const int jg  = tid >> 6;        // 0..3 -> 25 columns each
    const int j0  = jg * 25;

    float acc[25];
    #pragma unroll
    for (int jj = 0; jj < 25; jj++) acc[jj] = biasS[j0 + jj];

    #pragma unroll 2
    for (int i = 0; i < CDIM; i += 4) {
        float4 c = *reinterpret_cast<const float4*>(&condS[row][i]);
        #pragma unroll
        for (int jj = 0; jj < 25; jj++) {
            float4 w = *reinterpret_cast<const float4*>(&W1T[j0 + jj][i]); // warp-broadcast
            acc[jj] = fmaf(c.x, w.x, acc[jj]);
            acc[jj] = fmaf(c.y, w.y, acc[jj]);
            acc[jj] = fmaf(c.z, w.z, acc[jj]);
            acc[jj] = fmaf(c.w, w.w, acc[jj]);
        }
    }

    const int r = rowBase + row;
    #pragma unroll
    for (int jj = 0; jj < 25; jj++) {
        float a = acc[jj];
        a = a / (1.0f + __expf(-a));                       // silu
        g_H[(mlp * HID + j0 + jj) * M + r] = a;            // coalesced per jj
    }
}

// ---------------------------------------------------------------------------
// Kernel 2: fused GEMM2 + rational-quadratic spline.
// Grid: (M/256 row tiles, 64 dims). One thread = one (row, dim).
// W2 slices for this dim cached in smem and read via broadcast LDS.128.
// The s-network only evaluates the 2 needed columns (idx, idx+1 / wrap).
// ---------------------------------------------------------------------------
__global__ __launch_bounds__(256) void k2_spline(
    const float* __restrict__ x,
    const int*   __restrict__ pmask,
    const float* __restrict__ wW2, const float* __restrict__ wb2,
    const float* __restrict__ hW2, const float* __restrict__ hb2,
    const float* __restrict__ sW2, const float* __restrict__ sb2,
    float* __restrict__ out)
{
    __shared__ __align__(16) float sWw[HID][32];
    __shared__ __align__(16) float sWh[HID][32];
    __shared__ float sWs[HID][33];
    __shared__ float sbw[32], sbh[32], sbs[33];

    const int tid = threadIdx.x;
    const int d   = blockIdx.y;

    for (int idx = tid; idx < HID * 32; idx += 256) {
        int k = idx >> 5, j = idx & 31;
        sWw[k][j] = wW2[k * (DIMS * NBIN) + d * 32 + j];
        sWh[k][j] = hW2[k * (DIMS * NBIN) + d * 32 + j];
    }
    for (int idx = tid; idx < HID * 33; idx += 256) {
        int k = idx / 33, j = idx - k * 33;
        sWs[k][j] = sW2[k * (DIMS * (NBIN + 1)) + d * 33 + j];
    }
    if (tid < 32) { sbw[tid] = wb2[d * 32 + tid]; sbh[tid] = hb2[d * 32 + tid]; }
    if (tid < 33) { sbs[tid] = sb2[d * 33 + tid]; }
    __syncthreads();

    const int   r  = blockIdx.x * 256 + tid;
    const float xv = __ldg(&x[r * DIMS + d]);

    float acc[32];

    // ---------------- pass 1: width logits -> softmax -> bin search ----------
    #pragma unroll
    for (int j = 0; j < 32; j++) acc[j] = sbw[j];
    #pragma unroll 2
    for (int k = 0; k < HID; k++) {
        float hv = __ldg(&g_H[k * M + r]);
        const float4* row = reinterpret_cast<const float4*>(sWw[k]);
        #pragma unroll
        for (int q = 0; q < 8; q++) {
            float4 v = row[q];
            acc[4*q+0] = fmaf(hv, v.x, acc[4*q+0]);
            acc[4*q+1] = fmaf(hv, v.y, acc[4*q+1]);
            acc[4*q+2] = fmaf(hv, v.z, acc[4*q+2]);
            acc[4*q+3] = fmaf(hv, v.w, acc[4*q+3]);
        }
    }
    float mx = acc[0];
    #pragma unroll
    for (int j = 1; j < 32; j++) mx = fmaxf(mx, acc[j]);
    float S = 0.0f;
    #pragma unroll
    for (int j = 0; j < 32; j++) { acc[j] = __expf(acc[j] - mx); S += acc[j]; }
    float invS = 0.68f / S;  // (1 - EPS_BIN*NB) / S

    int   idx = 0;
    float cwk = -1.0f, cwn = 1.0f, cum = 0.0f;
    bool  found = false;
    #pragma unroll
    for (int j = 0; j < 32; j++) {
        float wj   = fmaf(acc[j], invS, 0.01f);
        cum += wj;
        float knot = (j == 31) ? 1.0f : fmaf(2.0f, cum, -1.0f);
        bool  ge   = (j < 31) && (xv >= knot);
        if (ge)             { idx = j + 1; cwk = knot; }
        if (!found && !ge)  { cwn = knot; found = true; }  // first knot > x == cw[idx+1]
    }
    float wk = cwn - cwk;

    // ---------------- pass 2: height logits -> softmax -> gather at idx ------
    #pragma unroll
    for (int j = 0; j < 32; j++) acc[j] = sbh[j];
    #pragma unroll 2
    for (int k = 0; k < HID; k++) {
        float hv = __ldg(&g_H[(HID + k) * M + r]);
        const float4* row = reinterpret_cast<const float4*>(sWh[k]);
        #pragma unroll
        for (int q = 0; q < 8; q++) {
            float4 v = row[q];
            acc[4*q+0] = fmaf(hv, v.x, acc[4*q+0]);
            acc[4*q+1] = fmaf(hv, v.y, acc[4*q+1]);
            acc[4*q+2] = fmaf(hv, v.z, acc[4*q+2]);
            acc[4*q+3] = fmaf(hv, v.w, acc[4*q+3]);
        }
    }
    float mx2 = acc[0];
    #pragma unroll
    for (int j = 1; j < 32; j++) mx2 = fmaxf(mx2, acc[j]);
    float S2 = 0.0f;
    #pragma unroll
    for (int j = 0; j < 32; j++) { acc[j] = __expf(acc[j] - mx2); S2 += acc[j]; }
    float invS2 = 0.68f / S2;

    float chk = -1.0f, chn = 1.0f;
    cum = 0.0f;
    #pragma unroll
    for (int j = 0; j < 32; j++) {
        float hj   = fmaf(acc[j], invS2, 0.01f);
        cum += hj;
        float knot = (j == 31) ? 1.0f : fmaf(2.0f, cum, -1.0f);
        if (j + 1 == idx) chk = knot;
        if (j     == idx) chn = knot;   // j==31 forced to 1.0 handles idx==31
    }
    float hk = chn - chk;

    // ---------------- pass 3: only the two needed derivative columns ---------
    int  pmd = __ldg(&pmask[d]);
    int  c1  = (pmd != 0 && idx == NBIN - 1) ? 0 : (idx + 1);
    float a0 = sbs[idx], a1 = sbs[c1];
    #pragma unroll 4
    for (int k = 0; k < HID; k++) {
        float hv = __ldg(&g_H[(2 * HID + k) * M + r]);
        float w0 = sWs[k][idx];
        float w1 = sWs[k][c1];
        a0 = fmaf(hv, w0, a0);
        a1 = fmaf(hv, w1, a1);
    }
    // softplus(v) = max(v,0) + log(1 + exp(-|v|))  (overflow-safe; arg of log in (1,2])
    float dk  = 0.01f + fmaxf(a0, 0.0f) + __logf(1.0f + __expf(-fabsf(a0)));
    float dk1 = 0.01f + fmaxf(a1, 0.0f) + __logf(1.0f + __expf(-fabsf(a1)));

    // ---------------- rational-quadratic evaluation --------------------------
    float delta = hk / wk;
    float theta = (xv - cwk) / wk;
    float omt   = 1.0f - theta;
    float t1m   = theta * omt;
    float denom = delta + (dk1 + dk - 2.0f * delta) * t1m;
    float th2   = theta * theta;
    float yv    = chk + hk * (delta * th2 + dk * t1m) / denom;
    float dnum  = dk1 * th2 + 2.0f * delta * t1m + dk * omt * omt;
    float deriv = (delta * delta) * dnum / (denom * denom);

    out[r * DIMS + d] = yv;
    g_ld[d * M + r]   = __logf(deriv);
}

// ---------------------------------------------------------------------------
// Kernel 3: deterministic ladJ reduction (sum of log-derivs over dims).
// ---------------------------------------------------------------------------
__global__ __launch_bounds__(256) void k3_ladj(float* __restrict__ out)
{
    int r = blockIdx.x * 256 + threadIdx.x;
    float s = 0.0f;
    #pragma unroll
    for (int d = 0; d < DIMS; d++) s += g_ld[d * M + r];
    out[M * DIMS + r] = s;
}

// ---------------------------------------------------------------------------
extern "C" void kernel_launch(void* const* d_in, const int* in_sizes, int n_in,
                              void* d_out, int out_size)
{
    const float* x    = (const float*)d_in[0];
    const float* cond = (const float*)d_in[1];
    const int*   pm   = (const int*)  d_in[2];
    const float* wW1  = (const float*)d_in[3];
    const float* wb1  = (const float*)d_in[4];
    const float* wW2  = (const float*)d_in[5];
    const float* wb2  = (const float*)d_in[6];
    const float* hW1  = (const float*)d_in[7];
    const float* hb1  = (const float*)d_in[8];
    const float* hW2  = (const float*)d_in[9];
    const float* hb2  = (const float*)d_in[10];
    const float* sW1  = (const float*)d_in[11];
    const float* sb1  = (const float*)d_in[12];
    const float* sW2  = (const float*)d_in[13];
    const float* sb2  = (const float*)d_in[14];
    float* out = (float*)d_out;

    k1_hidden<<<dim3(M / 64, 3), 256>>>(cond, wW1, wb1, hW1, hb1, sW1, sb1);
    k2_spline<<<dim3(M / 256, DIMS), 256>>>(x, pm, wW2, wb2, hW2, hb2, sW2, sb2, out);
    k3_ladj<<<M / 256, 256>>>(out);
}

// round 15
// speedup vs baseline: 1.1868x; 1.0604x over previous
#include <cuda_runtime.h>
#include <math.h>
#include <stdint.h>

// Problem constants (fixed by the reference setup_inputs)
#define M     16384
#define DIMS  64
#define NBIN  32
#define HID   100
#define CDIM  64

// Scratch (no cudaMalloc allowed)
__device__ float g_H [3 * HID * M];
__device__ float g_ld[DIMS * M];

// ---- packed f32x2 helpers (sm_103a FFMA2 path) -----------------------------
__device__ __forceinline__ uint64_t bcast2(float v) {
    uint32_t b = __float_as_uint(v);
    uint64_t r;
    asm("mov.b64 %0, {%1, %1};" : "=l"(r) : "r"(b));
    return r;
}
__device__ __forceinline__ uint64_t pack2(float lo, float hi) {
    uint64_t r;
    asm("mov.b64 %0, {%1, %2};" : "=l"(r) : "r"(__float_as_uint(lo)), "r"(__float_as_uint(hi)));
    return r;
}
__device__ __forceinline__ void fma2(uint64_t& d, uint64_t a, uint64_t b) {
    asm("fma.rn.f32x2 %0, %1, %2, %0;" : "+l"(d) : "l"(a), "l"(b));
}
__device__ __forceinline__ float lo32(uint64_t v) { return __uint_as_float((unsigned)v); }
__device__ __forceinline__ float hi32(uint64_t v) { return __uint_as_float((unsigned)(v >> 32)); }

// ---------------------------------------------------------------------------
// Kernel 1: H_T[j][r] = silu(cond[r,:] @ W1[:,j] + b1[j]) for the 3 MLPs.
// Grid: (M/64 row tiles, 3 MLPs). Packed f32x2 accumulation over the i-pairs.
// ---------------------------------------------------------------------------
__global__ __launch_bounds__(256) void k1_hidden(
    const float* __restrict__ cond,
    const float* __restrict__ wW1, const float* __restrict__ wb1,
    const float* __restrict__ hW1, const float* __restrict__ hb1,
    const float* __restrict__ sW1, const float* __restrict__ sb1)
{
    __shared__ __align__(16) float W1T [HID][68];   // [j][i]
    __shared__ __align__(16) float condS[64][68];   // [row][i]
    __shared__ float biasS[HID];

    const int tid     = threadIdx.x;
    const int mlp     = blockIdx.y;
    const int rowBase = blockIdx.x * 64;

    const float* W1 = (mlp == 0) ? wW1 : (mlp == 1) ? hW1 : sW1;
    const float* b1 = (mlp == 0) ? wb1 : (mlp == 1) ? hb1 : sb1;

    for (int idx = tid; idx < CDIM * HID; idx += 256) {
        int i = idx / HID, j = idx - i * HID;     // global read coalesced
        W1T[j][i] = W1[idx];
    }
    for (int idx = tid; idx < 64 * CDIM; idx += 256) {
        int rl = idx >> 6, i = idx & 63;
        condS[rl][i] = cond[(rowBase + rl) * CDIM + i];
    }
    if (tid < HID) biasS[tid] = b1[tid];
    __syncthreads();

    const int row = tid & 63;
    const int jg  = tid >> 6;        // 0..3 -> 25 columns each
    const int j0  = jg * 25;

    uint64_t acc2[25];               // lane0 = even-pair partial, lane1 = odd
    #pragma unroll
    for (int jj = 0; jj < 25; jj++)
        acc2[jj] = (uint64_t)__float_as_uint(biasS[j0 + jj]);  // bias in lane0

    #pragma unroll 2
    for (int i = 0; i < CDIM; i += 4) {
        ulonglong2 c2 = *reinterpret_cast<const ulonglong2*>(&condS[row][i]);
        #pragma unroll
        for (int jj = 0; jj < 25; jj++) {
            ulonglong2 w2 = *reinterpret_cast<const ulonglong2*>(&W1T[j0 + jj][i]);
            fma2(acc2[jj], c2.x, w2.x);
            fma2(acc2[jj], c2.y, w2.y);
        }
    }

    const int r = rowBase + row;
    #pragma unroll
    for (int jj = 0; jj < 25; jj++) {
        float a = lo32(acc2[jj]) + hi32(acc2[jj]);
        a = a / (1.0f + __expf(-a));                       // silu
        g_H[(mlp * HID + j0 + jj) * M + r] = a;            // coalesced per jj
    }
}

// ---------------------------------------------------------------------------
// Kernel 2: fused GEMM2 + rational-quadratic spline (packed f32x2 GEMVs).
// Grid: (M/256 row tiles, 64 dims). One thread = one (row, dim).
// ---------------------------------------------------------------------------
__global__ __launch_bounds__(256) void k2_spline(
    const float* __restrict__ x,
    const int*   __restrict__ pmask,
    const float* __restrict__ wW2, const float* __restrict__ wb2,
    const float* __restrict__ hW2, const float* __restrict__ hb2,
    const float* __restrict__ sW2, const float* __restrict__ sb2,
    float* __restrict__ out)
{
    __shared__ __align__(16) float sWw[HID][32];
    __shared__ __align__(16) float sWh[HID][32];
    __shared__ float sWs[HID][33];
    __shared__ __align__(16) float sbw[32];
    __shared__ __align__(16) float sbh[32];
    __shared__ float sbs[33];

    const int tid = threadIdx.x;
    const int d   = blockIdx.y;

    for (int idx = tid; idx < HID * 32; idx += 256) {
        int k = idx >> 5, j = idx & 31;
        sWw[k][j] = wW2[k * (DIMS * NBIN) + d * 32 + j];
        sWh[k][j] = hW2[k * (DIMS * NBIN) + d * 32 + j];
    }
    for (int idx = tid; idx < HID * 33; idx += 256) {
        int k = idx / 33, j = idx - k * 33;
        sWs[k][j] = sW2[k * (DIMS * (NBIN + 1)) + d * 33 + j];
    }
    if (tid < 32) { sbw[tid] = wb2[d * 32 + tid]; sbh[tid] = hb2[d * 32 + tid]; }
    if (tid < 33) { sbs[tid] = sb2[d * 33 + tid]; }
    __syncthreads();

    const int   r  = blockIdx.x * 256 + tid;
    const float xv = __ldg(&x[r * DIMS + d]);

    uint64_t acc2[16];
    float    acc[32];

    // ---------------- pass 1: width logits -> softmax -> bin search ----------
    {
        const uint64_t* b2 = reinterpret_cast<const uint64_t*>(sbw);
        #pragma unroll
        for (int q = 0; q < 16; q++) acc2[q] = b2[q];
    }
    #pragma unroll 4
    for (int k = 0; k < HID; k++) {
        uint64_t h2 = bcast2(__ldg(&g_H[k * M + r]));
        const ulonglong2* row = reinterpret_cast<const ulonglong2*>(sWw[k]);
        #pragma unroll
        for (int q = 0; q < 8; q++) {
            ulonglong2 v = row[q];
            fma2(acc2[2*q+0], h2, v.x);
            fma2(acc2[2*q+1], h2, v.y);
        }
    }
    #pragma unroll
    for (int q = 0; q < 16; q++) { acc[2*q] = lo32(acc2[q]); acc[2*q+1] = hi32(acc2[q]); }

    float mx = acc[0];
    #pragma unroll
    for (int j = 1; j < 32; j++) mx = fmaxf(mx, acc[j]);
    float S = 0.0f;
    #pragma unroll
    for (int j = 0; j < 32; j++) { acc[j] = __expf(acc[j] - mx); S += acc[j]; }
    float invS = 0.68f / S;  // (1 - EPS_BIN*NB) / S

    int   idx = 0;
    float cwk = -1.0f, cwn = 1.0f, cum = 0.0f;
    bool  found = false;
    #pragma unroll
    for (int j = 0; j < 32; j++) {
        float wj   = fmaf(acc[j], invS, 0.01f);
        cum += wj;
        float knot = (j == 31) ? 1.0f : fmaf(2.0f, cum, -1.0f);
        bool  ge   = (j < 31) && (xv >= knot);
        if (ge)             { idx = j + 1; cwk = knot; }
        if (!found && !ge)  { cwn = knot; found = true; }  // first knot > x == cw[idx+1]
    }
    float wk = cwn - cwk;

    // ---------------- pass 2: height logits -> softmax -> gather at idx ------
    {
        const uint64_t* b2 = reinterpret_cast<const uint64_t*>(sbh);
        #pragma unroll
        for (int q = 0; q < 16; q++) acc2[q] = b2[q];
    }
    #pragma unroll 4
    for (int k = 0; k < HID; k++) {
        uint64_t h2 = bcast2(__ldg(&g_H[(HID + k) * M + r]));
        const ulonglong2* row = reinterpret_cast<const ulonglong2*>(sWh[k]);
        #pragma unroll
        for (int q = 0; q < 8; q++) {
            ulonglong2 v = row[q];
            fma2(acc2[2*q+0], h2, v.x);
            fma2(acc2[2*q+1], h2, v.y);
        }
    }
    #pragma unroll
    for (int q = 0; q < 16; q++) { acc[2*q] = lo32(acc2[q]); acc[2*q+1] = hi32(acc2[q]); }

    float mx2 = acc[0];
    #pragma unroll
    for (int j = 1; j < 32; j++) mx2 = fmaxf(mx2, acc[j]);
    float S2 = 0.0f;
    #pragma unroll
    for (int j = 0; j < 32; j++) { acc[j] = __expf(acc[j] - mx2); S2 += acc[j]; }
    float invS2 = 0.68f / S2;

    float chk = -1.0f, chn = 1.0f;
    cum = 0.0f;
    #pragma unroll
    for (int j = 0; j < 32; j++) {
        float hj   = fmaf(acc[j], invS2, 0.01f);
        cum += hj;
        float knot = (j == 31) ? 1.0f : fmaf(2.0f, cum, -1.0f);
        if (j + 1 == idx) chk = knot;
        if (j     == idx) chn = knot;   // j==31 forced to 1.0 handles idx==31
    }
    float hk = chn - chk;

    // ---------------- pass 3: two derivative columns, packed into one f32x2 --
    int  pmd = __ldg(&pmask[d]);
    int  c1  = (pmd != 0 && idx == NBIN - 1) ? 0 : (idx + 1);
    uint64_t a01 = pack2(sbs[idx], sbs[c1]);   // lane0 = col idx, lane1 = col c1
    #pragma unroll 4
    for (int k = 0; k < HID; k++) {
        uint64_t h2 = bcast2(__ldg(&g_H[(2 * HID + k) * M + r]));
        uint64_t w2 = pack2(sWs[k][idx], sWs[k][c1]);
        fma2(a01, h2, w2);
    }
    float a0 = lo32(a01), a1 = hi32(a01);
    // softplus(v) = max(v,0) + log(1 + exp(-|v|))  (overflow-safe; log arg in (1,2])
    float dk  = 0.01f + fmaxf(a0, 0.0f) + __logf(1.0f + __expf(-fabsf(a0)));
    float dk1 = 0.01f + fmaxf(a1, 0.0f) + __logf(1.0f + __expf(-fabsf(a1)));

    // ---------------- rational-quadratic evaluation --------------------------
    float delta = hk / wk;
    float theta = (xv - cwk) / wk;
    float omt   = 1.0f - theta;
    float t1m   = theta * omt;
    float denom = delta + (dk1 + dk - 2.0f * delta) * t1m;
    float th2   = theta * theta;
    float yv    = chk + hk * (delta * th2 + dk * t1m) / denom;
    float dnum  = dk1 * th2 + 2.0f * delta * t1m + dk * omt * omt;
    float deriv = (delta * delta) * dnum / (denom * denom);

    out[r * DIMS + d] = yv;
    g_ld[d * M + r]   = __logf(deriv);
}

// ---------------------------------------------------------------------------
// Kernel 3: deterministic ladJ reduction (sum of log-derivs over dims).
// ---------------------------------------------------------------------------
__global__ __launch_bounds__(256) void k3_ladj(float* __restrict__ out)
{
    int r = blockIdx.x * 256 + threadIdx.x;
    float s = 0.0f;
    #pragma unroll
    for (int d = 0; d < DIMS; d++) s += g_ld[d * M + r];
    out[M * DIMS + r] = s;
}

// ---------------------------------------------------------------------------
extern "C" void kernel_launch(void* const* d_in, const int* in_sizes, int n_in,
                              void* d_out, int out_size)
{
    const float* x    = (const float*)d_in[0];
    const float* cond = (const float*)d_in[1];
    const int*   pm   = (const int*)  d_in[2];
    const float* wW1  = (const float*)d_in[3];
    const float* wb1  = (const float*)d_in[4];
    const float* wW2  = (const float*)d_in[5];
    const float* wb2  = (const float*)d_in[6];
    const float* hW1  = (const float*)d_in[7];
    const float* hb1  = (const float*)d_in[8];
    const float* hW2  = (const float*)d_in[9];
    const float* hb2  = (const float*)d_in[10];
    const float* sW1  = (const float*)d_in[11];
    const float* sb1  = (const float*)d_in[12];
    const float* sW2  = (const float*)d_in[13];
    const float* sb2  = (const float*)d_in[14];
    float* out = (float*)d_out;

    k1_hidden<<<dim3(M / 64, 3), 256>>>(cond, wW1, wb1, hW1, hb1, sW1, sb1);
    k2_spline<<<dim3(M / 256, DIMS), 256>>>(x, pm, wW2, wb2, hW2, hb2, sW2, sb2, out);
    k3_ladj<<<M / 256, 256>>>(out);
}